// round 1
// baseline (speedup 1.0000x reference)
#include <cuda_runtime.h>
#include <cuda_bf16.h>
#include <cstdint>

// Embedding gather: out[t, :] = weight[token_ids[t], :]
// d_in[0] = token_ids (int32), 8192 elements  [B=4, S=2048]
// d_in[1] = weight (float32), 32000 x 1024
// d_out   = float32, 8192 x 1024
//
// One CTA per token. 256 threads x float4 = 1024 floats = one row (4 KB).

static constexpr int D = 1024;
static constexpr int VEC = 4;                  // float4
static constexpr int THREADS = D / VEC;        // 256

__global__ __launch_bounds__(THREADS)
void embedding_gather_kernel(const int* __restrict__ token_ids,
                             const float4* __restrict__ weight,
                             float4* __restrict__ out,
                             int n_tokens) {
    int t = blockIdx.x;
    if (t >= n_tokens) return;

    int row = __ldg(token_ids + t);
    const float4* src = weight + (size_t)row * THREADS;
    float4* dst = out + (size_t)t * THREADS;

    dst[threadIdx.x] = __ldg(src + threadIdx.x);
}

extern "C" void kernel_launch(void* const* d_in, const int* in_sizes, int n_in,
                              void* d_out, int out_size) {
    const int* token_ids = (const int*)d_in[0];
    const float4* weight = (const float4*)d_in[1];
    float4* out = (float4*)d_out;

    int n_tokens = in_sizes[0];   // 8192

    embedding_gather_kernel<<<n_tokens, THREADS>>>(token_ids, weight, out, n_tokens);
}